// round 13
// baseline (speedup 1.0000x reference)
#include <cuda_runtime.h>

#define Ll 4096
#define Dd 128
#define Cc 32
#define NCH 128
#define BHh 16
#define DVB 8
#define NDVB 16
#define ELEMS (BHh*Ll*Dd)
#define O_ELEMS ((size_t)ELEMS)
#define NCHK (BHh*NCH)

// Scratch (__device__ globals)
__device__ float g_qn  [ELEMS];               // q normalized (epilogue)
__device__ float g_u   [ELEMS];               // u = T(v*beta) row-major (scan)
__device__ float g_wT36[NCHK*4608];           // per chunk: w^T [128][36] padded
__device__ float g_kT36[NCHK*4608];           // per chunk: k^T [128][36] padded
__device__ float g_att [NCHK*1024];           // attn_local (epilogue)
__device__ float g_S   [(size_t)NCHK*16384];  // per chunk: S_i col-major [c][d]
__device__ float g_u2  [NCHK*4096];           // per chunk: u' ROW-major [r][c]

__device__ __forceinline__ unsigned smem_u32(const void* p){
    unsigned a;
    asm("{ .reg .u64 t; cvta.to.shared.u64 t, %1; cvt.u32.u64 %0, t; }"
        : "=r"(a) : "l"(p));
    return a;
}
__device__ __forceinline__ void mbar_init(unsigned mbar, unsigned cnt){
    asm volatile("mbarrier.init.shared.b64 [%0], %1;" :: "r"(mbar), "r"(cnt) : "memory");
}
__device__ __forceinline__ void mbar_expect_tx(unsigned mbar, unsigned bytes){
    asm volatile("mbarrier.arrive.expect_tx.shared.b64 _, [%0], %1;"
                 :: "r"(mbar), "r"(bytes) : "memory");
}
__device__ __forceinline__ void tma_bulk_g2s(unsigned dst, const void* src,
                                             unsigned bytes, unsigned mbar){
    asm volatile("cp.async.bulk.shared::cta.global.mbarrier::complete_tx::bytes "
                 "[%0], [%1], %2, [%3];"
                 :: "r"(dst), "l"(src), "r"(bytes), "r"(mbar) : "memory");
}
__device__ __forceinline__ void mbar_wait(unsigned mbar, unsigned parity){
    asm volatile("{\n\t.reg .pred P;\n"
                 "WAIT_%=:\n\t"
                 "mbarrier.try_wait.parity.acquire.cta.shared::cta.b64 P, [%0], %1;\n\t"
                 "@!P bra WAIT_%=;\n\t}"
                 :: "r"(mbar), "r"(parity) : "memory");
}

// ----------------------------------------------------------------------------
// Kernel 1: per-chunk preprocessing. grid = 2048, block = 128  (unchanged)
// ----------------------------------------------------------------------------
__global__ __launch_bounds__(128) void prep_kernel(
    const float* __restrict__ q, const float* __restrict__ k,
    const float* __restrict__ v, const float* __restrict__ beta)
{
    extern __shared__ float sm1[];
    float* sqT   = sm1;                // [128][33]
    float* skT   = sqT + 4224;         // [128][33]
    float* svb   = skT + 4224;         // [32][128]
    float* sA    = svb + 4096;         // [32][33]
    float* sbeta = sA  + 1056;         // [32]

    const int tid  = threadIdx.x;
    const int lane = tid & 31;
    const int warp = tid >> 5;
    const int bh = blockIdx.x >> 7;
    const int ci = blockIdx.x & 127;
    const int chk = blockIdx.x;
    const size_t base = ((size_t)bh*Ll + (size_t)ci*Cc)*Dd;

    for (int r = warp*8; r < warp*8 + 8; ++r) {
        float bet = beta[(size_t)bh*Ll + ci*Cc + r];
        const float4 xq = *(const float4*)(q + base + r*Dd + lane*4);
        const float4 xk = *(const float4*)(k + base + r*Dd + lane*4);
        const float4 xv = *(const float4*)(v + base + r*Dd + lane*4);
        float s2q = xq.x*xq.x + xq.y*xq.y + xq.z*xq.z + xq.w*xq.w;
        float s2k = xk.x*xk.x + xk.y*xk.y + xk.z*xk.z + xk.w*xk.w;
        #pragma unroll
        for (int o = 16; o; o >>= 1) {
            s2q += __shfl_xor_sync(0xffffffffu, s2q, o);
            s2k += __shfl_xor_sync(0xffffffffu, s2k, o);
        }
        float iq = rsqrtf(s2q + 1e-6f);
        float ik = rsqrtf(s2k + 1e-6f);
        float4 nq = make_float4(xq.x*iq, xq.y*iq, xq.z*iq, xq.w*iq);
        float4 nk = make_float4(xk.x*ik, xk.y*ik, xk.z*ik, xk.w*ik);
        *(float4*)(g_qn + base + r*Dd + lane*4) = nq;
        const int d0 = lane*4;
        sqT[(d0+0)*33 + r] = nq.x; sqT[(d0+1)*33 + r] = nq.y;
        sqT[(d0+2)*33 + r] = nq.z; sqT[(d0+3)*33 + r] = nq.w;
        skT[(d0+0)*33 + r] = nk.x; skT[(d0+1)*33 + r] = nk.y;
        skT[(d0+2)*33 + r] = nk.z; skT[(d0+3)*33 + r] = nk.w;
        *(float4*)(svb + r*Dd + d0) = make_float4(xv.x*bet, xv.y*bet, xv.z*bet, xv.w*bet);
        if (lane == 0) sbeta[r] = bet;
    }
    __syncthreads();

    // k^T padded [128][36] (TMA target layout)
    {
        const int d = tid;
        #pragma unroll
        for (int r4 = 0; r4 < 32; r4 += 4) {
            *(float4*)&g_kT36[(size_t)chk*4608 + d*36 + r4] = make_float4(
                skT[d*33+r4], skT[d*33+r4+1], skT[d*33+r4+2], skT[d*33+r4+3]);
        }
    }

    // A = -beta_i (k_i.k_j) strict-lower ; E = q_i.k_j incl-lower -> g_att
    {
        const int i0 = (tid >> 3) * 2;
        const int j0 = (tid & 7) * 4;
        float a00=0,a01=0,a02=0,a03=0,a10=0,a11=0,a12=0,a13=0;
        float e00=0,e01=0,e02=0,e03=0,e10=0,e11=0,e12=0,e13=0;
        #pragma unroll 4
        for (int d = 0; d < Dd; ++d) {
            const float* kc = skT + d*33;
            const float* qc = sqT + d*33;
            float b0=kc[j0], b1=kc[j0+1], b2=kc[j0+2], b3=kc[j0+3];
            float ka0=kc[i0], ka1=kc[i0+1], qa0=qc[i0], qa1=qc[i0+1];
            a00+=ka0*b0; a01+=ka0*b1; a02+=ka0*b2; a03+=ka0*b3;
            a10+=ka1*b0; a11+=ka1*b1; a12+=ka1*b2; a13+=ka1*b3;
            e00+=qa0*b0; e01+=qa0*b1; e02+=qa0*b2; e03+=qa0*b3;
            e10+=qa1*b0; e11+=qa1*b1; e12+=qa1*b2; e13+=qa1*b3;
        }
        float nb0 = -sbeta[i0], nb1 = -sbeta[i0+1];
        sA[(i0  )*33+j0  ] = (j0  <i0  ) ? nb0*a00 : 0.f;
        sA[(i0  )*33+j0+1] = (j0+1<i0  ) ? nb0*a01 : 0.f;
        sA[(i0  )*33+j0+2] = (j0+2<i0  ) ? nb0*a02 : 0.f;
        sA[(i0  )*33+j0+3] = (j0+3<i0  ) ? nb0*a03 : 0.f;
        sA[(i0+1)*33+j0  ] = (j0  <i0+1) ? nb1*a10 : 0.f;
        sA[(i0+1)*33+j0+1] = (j0+1<i0+1) ? nb1*a11 : 0.f;
        sA[(i0+1)*33+j0+2] = (j0+2<i0+1) ? nb1*a12 : 0.f;
        sA[(i0+1)*33+j0+3] = (j0+3<i0+1) ? nb1*a13 : 0.f;
        float* ga = g_att + (size_t)chk*1024;
        ga[(i0  )*Cc+j0  ] = (j0  <=i0  ) ? e00 : 0.f;
        ga[(i0  )*Cc+j0+1] = (j0+1<=i0  ) ? e01 : 0.f;
        ga[(i0  )*Cc+j0+2] = (j0+2<=i0  ) ? e02 : 0.f;
        ga[(i0  )*Cc+j0+3] = (j0+3<=i0  ) ? e03 : 0.f;
        ga[(i0+1)*Cc+j0  ] = (j0  <=i0+1) ? e10 : 0.f;
        ga[(i0+1)*Cc+j0+1] = (j0+1<=i0+1) ? e11 : 0.f;
        ga[(i0+1)*Cc+j0+2] = (j0+2<=i0+1) ? e12 : 0.f;
        ga[(i0+1)*Cc+j0+3] = (j0+3<=i0+1) ? e13 : 0.f;
    }
    __syncthreads();

    // forward substitution (warp 0), then += I
    if (warp == 0) {
        for (int i = 1; i < 32; ++i) {
            float rv  = sA[i*33 + lane];
            float acc = rv;
            for (int j = 0; j < i; ++j)
                acc += __shfl_sync(0xffffffffu, rv, j) * sA[j*33 + lane];
            sA[i*33 + lane] = acc;
            __syncwarp();
        }
        sA[lane*33 + lane] += 1.0f;
    }
    __syncthreads();

    // u = T(v*beta) row-major ; w^T padded [128][36]
    {
        const int d = tid;
        #pragma unroll
        for (int rb = 0; rb < 4; ++rb) {
            const int r0 = rb*8;
            float ar[8];
            #pragma unroll
            for (int rr = 0; rr < 8; ++rr) ar[rr] = sA[(r0+rr)*33 + lane];
            float au[8] = {0,0,0,0,0,0,0,0};
            float aw[8] = {0,0,0,0,0,0,0,0};
            for (int j = 0; j < 32; ++j) {
                float vb = svb[j*Dd + d];
                float kb = skT[d*33 + j] * sbeta[j];
                #pragma unroll
                for (int rr = 0; rr < 8; ++rr) {
                    float a = __shfl_sync(0xffffffffu, ar[rr], j);
                    au[rr] += a*vb;
                    aw[rr] += a*kb;
                }
            }
            #pragma unroll
            for (int rr = 0; rr < 8; ++rr)
                g_u[base + (size_t)(r0+rr)*Dd + d] = au[rr];
            *(float4*)&g_wT36[(size_t)chk*4608 + d*36 + r0    ] = make_float4(aw[0],aw[1],aw[2],aw[3]);
            *(float4*)&g_wT36[(size_t)chk*4608 + d*36 + r0 + 4] = make_float4(aw[4],aw[5],aw[6],aw[7]);
        }
    }
}

// ----------------------------------------------------------------------------
// Kernel 2: sequential scan. grid = (16,16) = 256 CTAs, DVB=8, 2 CTAs/SM.
// TMA-bulk staging; independent barrier domains overlap per SM.
// ----------------------------------------------------------------------------
#define WST 36
#define SST 12
#define TILE_F 4608                 // floats per (w or k) buffer
#define TILE_B 18432                // bytes per tile

__global__ __launch_bounds__(512, 2) void scan_kernel(float* __restrict__ out)
{
    extern __shared__ float sm2[];
    float* swT = sm2;                   // [2][128][36] w^T
    float* skT = swT + 2*TILE_F;        // [2][128][36] k^T
    float* sS  = skT + 2*TILE_F;        // [128][12]
    float* sYp = sS  + 1536;            // [8][32][12]
    float* su2 = sYp + 3072;            // [32][12]
    float* smb = su2 + 384;             // mbarriers (2 x 8B)

    const int cb = blockIdx.x;          // 0..15
    const int bh = blockIdx.y;
    const int colbase = cb * DVB;
    const int tid  = threadIdx.x;
    const int lane = tid & 31;
    const int warp = tid >> 5;

    const unsigned sw_u32 = smem_u32(swT);
    const unsigned sk_u32 = smem_u32(skT);
    const unsigned mb_u32 = smem_u32(smb);

    // Y roles: dq = 16-d slice (0..7), cg4 = col half {0,4}; lane = r
    const int dq  = warp >> 1;
    const int cg4 = (warp & 1) * 4;
    // update roles: lane owns S[sd][uc2 .. uc2+1]
    const int sd  = (warp >> 2)*32 + lane;
    const int uc2 = (warp & 3) * 2;
    // u' roles (tid<256): r = tid>>3, c = tid&7
    const int upr = tid >> 3;
    const int upc = tid & 7;

    float2 Sreg = make_float2(0.f, 0.f);
    for (int i = tid; i < 1536; i += 512) sS[i] = 0.f;

    // init mbarriers + first fill
    if (tid == 0) { mbar_init(mb_u32, 1); mbar_init(mb_u32 + 8, 1); }
    __syncthreads();
    if (tid == 0) {
        const size_t tb = (size_t)(bh*NCH)*TILE_F;
        mbar_expect_tx(mb_u32, 2*TILE_B);
        tma_bulk_g2s(sw_u32, g_wT36 + tb, TILE_B, mb_u32);
        tma_bulk_g2s(sk_u32, g_kT36 + tb, TILE_B, mb_u32);
    }
    float ruu = 0.f;
    if (tid < 256)
        ruu = g_u[((size_t)bh*Ll + upr)*Dd + colbase + upc];

    for (int ci = 0; ci < NCH; ++ci) {
        const int buf = ci & 1;
        const int chk = bh*NCH + ci;

        // issue fill for chunk ci+1 into the other buffer
        if (tid == 0 && ci + 1 < NCH) {
            const int b2 = (ci + 1) & 1;
            const size_t tb = (size_t)(chk + 1)*TILE_F;
            mbar_expect_tx(mb_u32 + b2*8, 2*TILE_B);
            tma_bulk_g2s(sw_u32 + b2*TILE_B, g_wT36 + tb, TILE_B, mb_u32 + b2*8);
            tma_bulk_g2s(sk_u32 + b2*TILE_B, g_kT36 + tb, TILE_B, mb_u32 + b2*8);
        }
        // prefetch next u element
        float ru_next = ruu;
        if (tid < 256 && ci + 1 < NCH)
            ru_next = g_u[((size_t)bh*Ll + (size_t)(ci+1)*Cc + upr)*Dd + colbase + upc];

        // wait for this chunk's tiles
        mbar_wait(mb_u32 + buf*8, (unsigned)((ci >> 1) & 1));

        // persist S_i (pre-chunk), col-major [c][d]
        {
            float* gs = g_S + (size_t)chk*16384 + (size_t)(colbase + uc2)*128 + sd;
            gs[0] = Sreg.x; gs[128] = Sreg.y;
        }

        // Y: partial of w(32x128)@S(128x8); warp: d in [dq*16,+16), 4 cols
        {
            const float* xw = swT + buf*TILE_F;
            float4 y = make_float4(0,0,0,0);
            #pragma unroll
            for (int j = 0; j < 16; ++j) {
                const int jd = dq*16 + j;
                float x = xw[jd*WST + lane];
                float4 s = *(const float4*)&sS[jd*SST + cg4];
                y.x += x*s.x; y.y += x*s.y; y.z += x*s.z; y.w += x*s.w;
            }
            *(float4*)&sYp[dq*384 + lane*SST + cg4] = y;
        }
        __syncthreads();

        // u' = u - w@S  (threads 0..255, one element each)
        if (tid < 256) {
            float acc = ruu;
            #pragma unroll
            for (int d8 = 0; d8 < 8; ++d8)
                acc -= sYp[d8*384 + upr*SST + upc];
            su2[upr*SST + upc] = acc;
            g_u2[(size_t)chk*4096 + upr*128 + colbase + upc] = acc;   // row-major
        }
        __syncthreads();

        // S += k^T @ u'  (register-resident float2 S tile; vec k loads)
        {
            const float* kp = skT + buf*TILE_F + sd*WST;
            #pragma unroll
            for (int r4 = 0; r4 < 8; ++r4) {
                float4 k4 = *(const float4*)(kp + r4*4);
                float2 u0 = *(const float2*)&su2[(r4*4    )*SST + uc2];
                float2 u1 = *(const float2*)&su2[(r4*4 + 1)*SST + uc2];
                float2 u2 = *(const float2*)&su2[(r4*4 + 2)*SST + uc2];
                float2 u3 = *(const float2*)&su2[(r4*4 + 3)*SST + uc2];
                Sreg.x += k4.x*u0.x; Sreg.y += k4.x*u0.y;
                Sreg.x += k4.y*u1.x; Sreg.y += k4.y*u1.y;
                Sreg.x += k4.z*u2.x; Sreg.y += k4.z*u2.y;
                Sreg.x += k4.w*u3.x; Sreg.y += k4.w*u3.y;
            }
            *(float2*)&sS[sd*SST + uc2] = Sreg;
        }
        ruu = ru_next;
        __syncthreads();
    }

    // final S -> out
    {
        float* o = out + O_ELEMS + ((size_t)bh*Dd + sd)*Dd + colbase + uc2;
        o[0] = Sreg.x; o[1] = Sreg.y;
    }
}

// ----------------------------------------------------------------------------
// Kernel 3: epilogue o = q@S_i + A@u'_i. grid = (NCH, BHh), block = 256.
// ----------------------------------------------------------------------------
#define AST 36

__global__ __launch_bounds__(256) void epi_kernel(float* __restrict__ out)
{
    extern __shared__ float sm3[];
    float* sS = sm3;              // [128][132]
    float* sq = sS + 128*132;     // [32][132]
    float* su = sq + 32*132;      // [32][132]
    float* sA = su + 32*132;      // [32][36]

    const int ci = blockIdx.x;
    const int bh = blockIdx.y;
    const int chk = bh*NCH + ci;
    const int tid = threadIdx.x;
    const size_t qbase = ((size_t)bh*Ll + (size_t)ci*Cc)*Dd;

    // stage S (col-major gmem -> row-major smem)
    {
        const int c = tid >> 1;
        const int db = (tid & 1) * 64;
        const float* gs = g_S + (size_t)chk*16384 + (size_t)c*128 + db;
        #pragma unroll
        for (int i = 0; i < 16; ++i) {
            float4 f = *(const float4*)(gs + i*4);
            int d = db + i*4;
            sS[(d  )*132 + c] = f.x; sS[(d+1)*132 + c] = f.y;
            sS[(d+2)*132 + c] = f.z; sS[(d+3)*132 + c] = f.w;
        }
    }
    // stage q (row-major)
    {
        #pragma unroll
        for (int t = 0; t < 4; ++t) {
            int i4 = (tid + t*256) * 4;
            float4 f = *(const float4*)(g_qn + qbase + i4);
            *(float4*)&sq[(i4 >> 7)*132 + (i4 & 127)] = f;
        }
    }
    // stage u' (row-major, straight copy)
    {
        #pragma unroll
        for (int t = 0; t < 4; ++t) {
            int i4 = (tid + t*256) * 4;
            float4 f = *(const float4*)(g_u2 + (size_t)chk*4096 + i4);
            *(float4*)&su[(i4 >> 7)*132 + (i4 & 127)] = f;
        }
    }
    // stage A (stride 36)
    {
        int i4 = tid * 4;
        float4 f = *(const float4*)(g_att + (size_t)chk*1024 + i4);
        *(float4*)&sA[(i4 >> 5)*AST + (i4 & 31)] = f;
    }
    __syncthreads();

    const int m0 = (tid >> 4) * 2;
    const int m1 = m0 + 1;
    const int cbk = (tid & 15) * 8;
    float4 a00 = make_float4(0,0,0,0), a01 = a00, a10 = a00, a11 = a00;
    #pragma unroll 8
    for (int d = 0; d < 128; ++d) {
        float q0 = sq[m0*132 + d];
        float q1 = sq[m1*132 + d];
        float4 s0 = *(const float4*)&sS[d*132 + cbk];
        float4 s1 = *(const float4*)&sS[d*132 + cbk + 4];
        a00.x += q0*s0.x; a00.y += q0*s0.y; a00.z += q0*s0.z; a00.w += q0*s0.w;
        a01.x += q0*s1.x; a01.y += q0*s1.y; a01.z += q0*s1.z; a01.w += q0*s1.w;
        a10.x += q1*s0.x; a10.y += q1*s0.y; a10.z += q1*s0.z; a10.w += q1*s0.w;
        a11.x += q1*s1.x; a11.y += q1*s1.y; a11.z += q1*s1.z; a11.w += q1*s1.w;
    }
    #pragma unroll 8
    for (int j = 0; j < 32; ++j) {
        float p0 = sA[m0*AST + j];
        float p1 = sA[m1*AST + j];
        float4 u0 = *(const float4*)&su[j*132 + cbk];
        float4 u1 = *(const float4*)&su[j*132 + cbk + 4];
        a00.x += p0*u0.x; a00.y += p0*u0.y; a00.z += p0*u0.z; a00.w += p0*u0.w;
        a01.x += p0*u1.x; a01.y += p0*u1.y; a01.z += p0*u1.z; a01.w += p0*u1.w;
        a10.x += p1*u0.x; a10.y += p1*u0.y; a10.z += p1*u0.z; a10.w += p1*u0.w;
        a11.x += p1*u1.x; a11.y += p1*u1.y; a11.z += p1*u1.z; a11.w += p1*u1.w;
    }
    float* o0 = out + qbase + (size_t)m0*Dd + cbk;
    float* o1 = out + qbase + (size_t)m1*Dd + cbk;
    *(float4*)(o0)     = a00; *(float4*)(o0 + 4) = a01;
    *(float4*)(o1)     = a10; *(float4*)(o1 + 4) = a11;
}

// ----------------------------------------------------------------------------
extern "C" void kernel_launch(void* const* d_in, const int* in_sizes, int n_in,
                              void* d_out, int out_size)
{
    const float* q    = (const float*)d_in[0];
    const float* k    = (const float*)d_in[1];
    const float* v    = (const float*)d_in[2];
    const float* beta = (const float*)d_in[3];
    float* out = (float*)d_out;

    const int smem1 = (2*4224 + 4096 + 1056 + 32) * 4;                 // 54528
    const int smem2 = (4*TILE_F + 1536 + 3072 + 384 + 4) * 4;          // 93680
    const int smem3 = (128*132 + 32*132 + 32*132 + 32*AST) * 4;        // 105984
    cudaFuncSetAttribute(prep_kernel, cudaFuncAttributeMaxDynamicSharedMemorySize, smem1);
    cudaFuncSetAttribute(scan_kernel, cudaFuncAttributeMaxDynamicSharedMemorySize, smem2);
    cudaFuncSetAttribute(epi_kernel,  cudaFuncAttributeMaxDynamicSharedMemorySize, smem3);

    prep_kernel<<<NCHK, 128, smem1>>>(q, k, v, beta);
    scan_kernel<<<dim3(NDVB, BHh), 512, smem2>>>(out);
    epi_kernel<<<dim3(NCH, BHh), 256, smem3>>>(out);
}

// round 14
// speedup vs baseline: 1.0131x; 1.0131x over previous
#include <cuda_runtime.h>

#define Ll 4096
#define Dd 128
#define Cc 32
#define NCH 128
#define BHh 16
#define DVB 16
#define NDVB 8
#define ELEMS (BHh*Ll*Dd)
#define O_ELEMS ((size_t)ELEMS)
#define NCHK (BHh*NCH)

// Scratch (__device__ globals)
__device__ float g_qn  [ELEMS];               // q normalized (epilogue)
__device__ float g_u   [ELEMS];               // u = T(v*beta) row-major (scan)
__device__ float g_wT36[NCHK*4608];           // per chunk: w^T [128][36] padded
__device__ float g_kT36[NCHK*4608];           // per chunk: k^T [128][36] padded
__device__ float g_att [NCHK*1024];           // attn_local (epilogue)
__device__ float g_S   [(size_t)NCHK*16384];  // per chunk: S_i col-major [c][d]
__device__ float g_u2  [NCHK*4096];           // per chunk: u' ROW-major [r][c]

__device__ __forceinline__ unsigned smem_u32(const void* p){
    unsigned a;
    asm("{ .reg .u64 t; cvta.to.shared.u64 t, %1; cvt.u32.u64 %0, t; }"
        : "=r"(a) : "l"(p));
    return a;
}
__device__ __forceinline__ void mbar_init(unsigned mbar, unsigned cnt){
    asm volatile("mbarrier.init.shared.b64 [%0], %1;" :: "r"(mbar), "r"(cnt) : "memory");
}
__device__ __forceinline__ void mbar_expect_tx(unsigned mbar, unsigned bytes){
    asm volatile("mbarrier.arrive.expect_tx.shared.b64 _, [%0], %1;"
                 :: "r"(mbar), "r"(bytes) : "memory");
}
__device__ __forceinline__ void tma_bulk_g2s(unsigned dst, const void* src,
                                             unsigned bytes, unsigned mbar){
    asm volatile("cp.async.bulk.shared::cta.global.mbarrier::complete_tx::bytes "
                 "[%0], [%1], %2, [%3];"
                 :: "r"(dst), "l"(src), "r"(bytes), "r"(mbar) : "memory");
}
__device__ __forceinline__ void mbar_wait(unsigned mbar, unsigned parity){
    asm volatile("{\n\t.reg .pred P;\n"
                 "WAIT_%=:\n\t"
                 "mbarrier.try_wait.parity.acquire.cta.shared::cta.b64 P, [%0], %1;\n\t"
                 "@!P bra WAIT_%=;\n\t}"
                 :: "r"(mbar), "r"(parity) : "memory");
}

// ----------------------------------------------------------------------------
// Kernel 1: per-chunk preprocessing. grid = 2048, block = 128  (unchanged)
// ----------------------------------------------------------------------------
__global__ __launch_bounds__(128) void prep_kernel(
    const float* __restrict__ q, const float* __restrict__ k,
    const float* __restrict__ v, const float* __restrict__ beta)
{
    extern __shared__ float sm1[];
    float* sqT   = sm1;                // [128][33]
    float* skT   = sqT + 4224;         // [128][33]
    float* svb   = skT + 4224;         // [32][128]
    float* sA    = svb + 4096;         // [32][33]
    float* sbeta = sA  + 1056;         // [32]

    const int tid  = threadIdx.x;
    const int lane = tid & 31;
    const int warp = tid >> 5;
    const int bh = blockIdx.x >> 7;
    const int ci = blockIdx.x & 127;
    const int chk = blockIdx.x;
    const size_t base = ((size_t)bh*Ll + (size_t)ci*Cc)*Dd;

    for (int r = warp*8; r < warp*8 + 8; ++r) {
        float bet = beta[(size_t)bh*Ll + ci*Cc + r];
        const float4 xq = *(const float4*)(q + base + r*Dd + lane*4);
        const float4 xk = *(const float4*)(k + base + r*Dd + lane*4);
        const float4 xv = *(const float4*)(v + base + r*Dd + lane*4);
        float s2q = xq.x*xq.x + xq.y*xq.y + xq.z*xq.z + xq.w*xq.w;
        float s2k = xk.x*xk.x + xk.y*xk.y + xk.z*xk.z + xk.w*xk.w;
        #pragma unroll
        for (int o = 16; o; o >>= 1) {
            s2q += __shfl_xor_sync(0xffffffffu, s2q, o);
            s2k += __shfl_xor_sync(0xffffffffu, s2k, o);
        }
        float iq = rsqrtf(s2q + 1e-6f);
        float ik = rsqrtf(s2k + 1e-6f);
        float4 nq = make_float4(xq.x*iq, xq.y*iq, xq.z*iq, xq.w*iq);
        float4 nk = make_float4(xk.x*ik, xk.y*ik, xk.z*ik, xk.w*ik);
        *(float4*)(g_qn + base + r*Dd + lane*4) = nq;
        const int d0 = lane*4;
        sqT[(d0+0)*33 + r] = nq.x; sqT[(d0+1)*33 + r] = nq.y;
        sqT[(d0+2)*33 + r] = nq.z; sqT[(d0+3)*33 + r] = nq.w;
        skT[(d0+0)*33 + r] = nk.x; skT[(d0+1)*33 + r] = nk.y;
        skT[(d0+2)*33 + r] = nk.z; skT[(d0+3)*33 + r] = nk.w;
        *(float4*)(svb + r*Dd + d0) = make_float4(xv.x*bet, xv.y*bet, xv.z*bet, xv.w*bet);
        if (lane == 0) sbeta[r] = bet;
    }
    __syncthreads();

    // k^T padded [128][36] (TMA target layout)
    {
        const int d = tid;
        #pragma unroll
        for (int r4 = 0; r4 < 32; r4 += 4) {
            *(float4*)&g_kT36[(size_t)chk*4608 + d*36 + r4] = make_float4(
                skT[d*33+r4], skT[d*33+r4+1], skT[d*33+r4+2], skT[d*33+r4+3]);
        }
    }

    // A = -beta_i (k_i.k_j) strict-lower ; E = q_i.k_j incl-lower -> g_att
    {
        const int i0 = (tid >> 3) * 2;
        const int j0 = (tid & 7) * 4;
        float a00=0,a01=0,a02=0,a03=0,a10=0,a11=0,a12=0,a13=0;
        float e00=0,e01=0,e02=0,e03=0,e10=0,e11=0,e12=0,e13=0;
        #pragma unroll 4
        for (int d = 0; d < Dd; ++d) {
            const float* kc = skT + d*33;
            const float* qc = sqT + d*33;
            float b0=kc[j0], b1=kc[j0+1], b2=kc[j0+2], b3=kc[j0+3];
            float ka0=kc[i0], ka1=kc[i0+1], qa0=qc[i0], qa1=qc[i0+1];
            a00+=ka0*b0; a01+=ka0*b1; a02+=ka0*b2; a03+=ka0*b3;
            a10+=ka1*b0; a11+=ka1*b1; a12+=ka1*b2; a13+=ka1*b3;
            e00+=qa0*b0; e01+=qa0*b1; e02+=qa0*b2; e03+=qa0*b3;
            e10+=qa1*b0; e11+=qa1*b1; e12+=qa1*b2; e13+=qa1*b3;
        }
        float nb0 = -sbeta[i0], nb1 = -sbeta[i0+1];
        sA[(i0  )*33+j0  ] = (j0  <i0  ) ? nb0*a00 : 0.f;
        sA[(i0  )*33+j0+1] = (j0+1<i0  ) ? nb0*a01 : 0.f;
        sA[(i0  )*33+j0+2] = (j0+2<i0  ) ? nb0*a02 : 0.f;
        sA[(i0  )*33+j0+3] = (j0+3<i0  ) ? nb0*a03 : 0.f;
        sA[(i0+1)*33+j0  ] = (j0  <i0+1) ? nb1*a10 : 0.f;
        sA[(i0+1)*33+j0+1] = (j0+1<i0+1) ? nb1*a11 : 0.f;
        sA[(i0+1)*33+j0+2] = (j0+2<i0+1) ? nb1*a12 : 0.f;
        sA[(i0+1)*33+j0+3] = (j0+3<i0+1) ? nb1*a13 : 0.f;
        float* ga = g_att + (size_t)chk*1024;
        ga[(i0  )*Cc+j0  ] = (j0  <=i0  ) ? e00 : 0.f;
        ga[(i0  )*Cc+j0+1] = (j0+1<=i0  ) ? e01 : 0.f;
        ga[(i0  )*Cc+j0+2] = (j0+2<=i0  ) ? e02 : 0.f;
        ga[(i0  )*Cc+j0+3] = (j0+3<=i0  ) ? e03 : 0.f;
        ga[(i0+1)*Cc+j0  ] = (j0  <=i0+1) ? e10 : 0.f;
        ga[(i0+1)*Cc+j0+1] = (j0+1<=i0+1) ? e11 : 0.f;
        ga[(i0+1)*Cc+j0+2] = (j0+2<=i0+1) ? e12 : 0.f;
        ga[(i0+1)*Cc+j0+3] = (j0+3<=i0+1) ? e13 : 0.f;
    }
    __syncthreads();

    // forward substitution (warp 0), then += I
    if (warp == 0) {
        for (int i = 1; i < 32; ++i) {
            float rv  = sA[i*33 + lane];
            float acc = rv;
            for (int j = 0; j < i; ++j)
                acc += __shfl_sync(0xffffffffu, rv, j) * sA[j*33 + lane];
            sA[i*33 + lane] = acc;
            __syncwarp();
        }
        sA[lane*33 + lane] += 1.0f;
    }
    __syncthreads();

    // u = T(v*beta) row-major ; w^T padded [128][36]
    {
        const int d = tid;
        #pragma unroll
        for (int rb = 0; rb < 4; ++rb) {
            const int r0 = rb*8;
            float ar[8];
            #pragma unroll
            for (int rr = 0; rr < 8; ++rr) ar[rr] = sA[(r0+rr)*33 + lane];
            float au[8] = {0,0,0,0,0,0,0,0};
            float aw[8] = {0,0,0,0,0,0,0,0};
            for (int j = 0; j < 32; ++j) {
                float vb = svb[j*Dd + d];
                float kb = skT[d*33 + j] * sbeta[j];
                #pragma unroll
                for (int rr = 0; rr < 8; ++rr) {
                    float a = __shfl_sync(0xffffffffu, ar[rr], j);
                    au[rr] += a*vb;
                    aw[rr] += a*kb;
                }
            }
            #pragma unroll
            for (int rr = 0; rr < 8; ++rr)
                g_u[base + (size_t)(r0+rr)*Dd + d] = au[rr];
            *(float4*)&g_wT36[(size_t)chk*4608 + d*36 + r0    ] = make_float4(aw[0],aw[1],aw[2],aw[3]);
            *(float4*)&g_wT36[(size_t)chk*4608 + d*36 + r0 + 4] = make_float4(aw[4],aw[5],aw[6],aw[7]);
        }
    }
}

// ----------------------------------------------------------------------------
// Kernel 2: sequential scan. grid = (8,16), block = 1024 (32 warps), DVB=16.
// TMA staging; Y S-operand is warp-broadcast; update in float2 across 32 warps.
// ----------------------------------------------------------------------------
#define WST 36
#define SST 20
#define TILE_F 4608                 // floats per (w or k) buffer
#define TILE_B 18432                // bytes per tile

__global__ __launch_bounds__(1024, 1) void scan_kernel(float* __restrict__ out)
{
    extern __shared__ float sm2[];
    float* swT = sm2;                   // [2][128][36] w^T
    float* skT = swT + 2*TILE_F;        // [2][128][36] k^T
    float* sS  = skT + 2*TILE_F;        // [128][20]
    float* sYp = sS  + 2560;            // [8][32][20]
    float* su2 = sYp + 5120;            // [32][20]
    float* smb = su2 + 640;             // mbarriers (2 x 8B)

    const int cb = blockIdx.x;
    const int bh = blockIdx.y;
    const int colbase = cb * DVB;
    const int tid  = threadIdx.x;
    const int lane = tid & 31;
    const int warp = tid >> 5;

    const unsigned sw_u32 = smem_u32(swT);
    const unsigned sk_u32 = smem_u32(skT);
    const unsigned mb_u32 = smem_u32(smb);

    // Y roles (32 warps): dq = 16-d slice (0..7), cg4 = col group *4 (0..12)
    const int dq  = warp >> 2;
    const int cg4 = (warp & 3) * 4;
    // update roles (32 warps): sd = d row, uc2 = col pair
    const int sd  = (warp >> 3)*32 + lane;   // (warp>>3) in 0..3
    const int uc2 = (warp & 7) * 2;          // 0,2,...,14
    // u' roles (tid<512): r = tid>>4, c = tid&15
    const int upr = tid >> 4;
    const int upc = tid & 15;

    float2 Sreg = make_float2(0.f, 0.f);
    for (int i = tid; i < 2560; i += 1024) sS[i] = 0.f;

    // init mbarriers + first fill
    if (tid == 0) { mbar_init(mb_u32, 1); mbar_init(mb_u32 + 8, 1); }
    __syncthreads();
    if (tid == 0) {
        const size_t tb = (size_t)(bh*NCH)*TILE_F;
        mbar_expect_tx(mb_u32, 2*TILE_B);
        tma_bulk_g2s(sw_u32, g_wT36 + tb, TILE_B, mb_u32);
        tma_bulk_g2s(sk_u32, g_kT36 + tb, TILE_B, mb_u32);
    }
    float ruu = 0.f;
    if (tid < 512)
        ruu = g_u[((size_t)bh*Ll + upr)*Dd + colbase + upc];

    for (int ci = 0; ci < NCH; ++ci) {
        const int buf = ci & 1;
        const int chk = bh*NCH + ci;

        // issue fill for chunk ci+1 into the other buffer
        if (tid == 0 && ci + 1 < NCH) {
            const int b2 = (ci + 1) & 1;
            const size_t tb = (size_t)(chk + 1)*TILE_F;
            mbar_expect_tx(mb_u32 + b2*8, 2*TILE_B);
            tma_bulk_g2s(sw_u32 + b2*TILE_B, g_wT36 + tb, TILE_B, mb_u32 + b2*8);
            tma_bulk_g2s(sk_u32 + b2*TILE_B, g_kT36 + tb, TILE_B, mb_u32 + b2*8);
        }
        // persist S_i (pre-chunk) from registers, col-major [c][d]
        {
            float* gs = g_S + (size_t)chk*16384 + (size_t)(colbase + uc2)*128 + sd;
            gs[0] = Sreg.x; gs[128] = Sreg.y;
        }
        // prefetch next u element
        float ru_next = ruu;
        if (tid < 512 && ci + 1 < NCH)
            ru_next = g_u[((size_t)bh*Ll + (size_t)(ci+1)*Cc + upr)*Dd + colbase + upc];

        // wait for this chunk's tiles
        mbar_wait(mb_u32 + buf*8, (unsigned)((ci >> 1) & 1));

        // Y: partial of w(32x128)@S(128x16); warp: d in [dq*16,+16), 4 cols
        {
            const float* xw = swT + buf*TILE_F;
            float4 y = make_float4(0,0,0,0);
            #pragma unroll
            for (int j = 0; j < 16; ++j) {
                const int jd = dq*16 + j;
                float x = xw[jd*WST + lane];
                float4 s = *(const float4*)&sS[jd*SST + cg4];   // warp-broadcast
                y.x += x*s.x; y.y += x*s.y; y.z += x*s.z; y.w += x*s.w;
            }
            *(float4*)&sYp[dq*640 + lane*SST + cg4] = y;
        }
        __syncthreads();

        // u' = u - w@S  (threads 0..511, one element each)
        if (tid < 512) {
            float acc = ruu;
            #pragma unroll
            for (int d8 = 0; d8 < 8; ++d8)
                acc -= sYp[d8*640 + upr*SST + upc];
            su2[upr*SST + upc] = acc;
            g_u2[(size_t)chk*4096 + upr*128 + colbase + upc] = acc;   // row-major
        }
        __syncthreads();

        // S += k^T @ u'  (32 warps, 32d x 2c float2 tiles; vec k loads)
        {
            const float* kp = skT + buf*TILE_F + sd*WST;
            #pragma unroll
            for (int r4 = 0; r4 < 8; ++r4) {
                float4 k4 = *(const float4*)(kp + r4*4);
                float2 u0 = *(const float2*)&su2[(r4*4    )*SST + uc2];
                float2 u1 = *(const float2*)&su2[(r4*4 + 1)*SST + uc2];
                float2 u2 = *(const float2*)&su2[(r4*4 + 2)*SST + uc2];
                float2 u3 = *(const float2*)&su2[(r4*4 + 3)*SST + uc2];
                Sreg.x += k4.x*u0.x; Sreg.y += k4.x*u0.y;
                Sreg.x += k4.y*u1.x; Sreg.y += k4.y*u1.y;
                Sreg.x += k4.z*u2.x; Sreg.y += k4.z*u2.y;
                Sreg.x += k4.w*u3.x; Sreg.y += k4.w*u3.y;
            }
            *(float2*)&sS[sd*SST + uc2] = Sreg;
        }
        ruu = ru_next;
        __syncthreads();
    }

    // final S -> out
    {
        float* o = out + O_ELEMS + ((size_t)bh*Dd + sd)*Dd + colbase + uc2;
        o[0] = Sreg.x; o[1] = Sreg.y;
    }
}

// ----------------------------------------------------------------------------
// Kernel 3: epilogue o = q@S_i + A@u'_i. grid = (NCH, BHh), block = 256.
// ----------------------------------------------------------------------------
#define AST 36

__global__ __launch_bounds__(256) void epi_kernel(float* __restrict__ out)
{
    extern __shared__ float sm3[];
    float* sS = sm3;              // [128][132]
    float* sq = sS + 128*132;     // [32][132]
    float* su = sq + 32*132;      // [32][132]
    float* sA = su + 32*132;      // [32][36]

    const int ci = blockIdx.x;
    const int bh = blockIdx.y;
    const int chk = bh*NCH + ci;
    const int tid = threadIdx.x;
    const size_t qbase = ((size_t)bh*Ll + (size_t)ci*Cc)*Dd;

    // stage S (col-major gmem -> row-major smem)
    {
        const int c = tid >> 1;
        const int db = (tid & 1) * 64;
        const float* gs = g_S + (size_t)chk*16384 + (size_t)c*128 + db;
        #pragma unroll
        for (int i = 0; i < 16; ++i) {
            float4 f = *(const float4*)(gs + i*4);
            int d = db + i*4;
            sS[(d  )*132 + c] = f.x; sS[(d+1)*132 + c] = f.y;
            sS[(d+2)*132 + c] = f.z; sS[(d+3)*132 + c] = f.w;
        }
    }
    // stage q (row-major)
    {
        #pragma unroll
        for (int t = 0; t < 4; ++t) {
            int i4 = (tid + t*256) * 4;
            float4 f = *(const float4*)(g_qn + qbase + i4);
            *(float4*)&sq[(i4 >> 7)*132 + (i4 & 127)] = f;
        }
    }
    // stage u' (row-major, straight copy)
    {
        #pragma unroll
        for (int t = 0; t < 4; ++t) {
            int i4 = (tid + t*256) * 4;
            float4 f = *(const float4*)(g_u2 + (size_t)chk*4096 + i4);
            *(float4*)&su[(i4 >> 7)*132 + (i4 & 127)] = f;
        }
    }
    // stage A (stride 36)
    {
        int i4 = tid * 4;
        float4 f = *(const float4*)(g_att + (size_t)chk*1024 + i4);
        *(float4*)&sA[(i4 >> 5)*AST + (i4 & 31)] = f;
    }
    __syncthreads();

    const int m0 = (tid >> 4) * 2;
    const int m1 = m0 + 1;
    const int cbk = (tid & 15) * 8;
    float4 a00 = make_float4(0,0,0,0), a01 = a00, a10 = a00, a11 = a00;
    #pragma unroll 8
    for (int d = 0; d < 128; ++d) {
        float q0 = sq[m0*132 + d];
        float q1 = sq[m1*132 + d];
        float4 s0 = *(const float4*)&sS[d*132 + cbk];
        float4 s1 = *(const float4*)&sS[d*132 + cbk + 4];
        a00.x += q0*s0.x; a00.y += q0*s0.y; a00.z += q0*s0.z; a00.w += q0*s0.w;
        a01.x += q0*s1.x; a01.y += q0*s1.y; a01.z += q0*s1.z; a01.w += q0*s1.w;
        a10.x += q1*s0.x; a10.y += q1*s0.y; a10.z += q1*s0.z; a10.w += q1*s0.w;
        a11.x += q1*s1.x; a11.y += q1*s1.y; a11.z += q1*s1.z; a11.w += q1*s1.w;
    }
    #pragma unroll 8
    for (int j = 0; j < 32; ++j) {
        float p0 = sA[m0*AST + j];
        float p1 = sA[m1*AST + j];
        float4 u0 = *(const float4*)&su[j*132 + cbk];
        float4 u1 = *(const float4*)&su[j*132 + cbk + 4];
        a00.x += p0*u0.x; a00.y += p0*u0.y; a00.z += p0*u0.z; a00.w += p0*u0.w;
        a01.x += p0*u1.x; a01.y += p0*u1.y; a01.z += p0*u1.z; a01.w += p0*u1.w;
        a10.x += p1*u0.x; a10.y += p1*u0.y; a10.z += p1*u0.z; a10.w += p1*u0.w;
        a11.x += p1*u1.x; a11.y += p1*u1.y; a11.z += p1*u1.z; a11.w += p1*u1.w;
    }
    float* o0 = out + qbase + (size_t)m0*Dd + cbk;
    float* o1 = out + qbase + (size_t)m1*Dd + cbk;
    *(float4*)(o0)     = a00; *(float4*)(o0 + 4) = a01;
    *(float4*)(o1)     = a10; *(float4*)(o1 + 4) = a11;
}

// ----------------------------------------------------------------------------
extern "C" void kernel_launch(void* const* d_in, const int* in_sizes, int n_in,
                              void* d_out, int out_size)
{
    const float* q    = (const float*)d_in[0];
    const float* k    = (const float*)d_in[1];
    const float* v    = (const float*)d_in[2];
    const float* beta = (const float*)d_in[3];
    float* out = (float*)d_out;

    const int smem1 = (2*4224 + 4096 + 1056 + 32) * 4;                 // 54528
    const int smem2 = (4*TILE_F + 2560 + 5120 + 640 + 8) * 4;          // 107040
    const int smem3 = (128*132 + 32*132 + 32*132 + 32*AST) * 4;        // 105984
    cudaFuncSetAttribute(prep_kernel, cudaFuncAttributeMaxDynamicSharedMemorySize, smem1);
    cudaFuncSetAttribute(scan_kernel, cudaFuncAttributeMaxDynamicSharedMemorySize, smem2);
    cudaFuncSetAttribute(epi_kernel,  cudaFuncAttributeMaxDynamicSharedMemorySize, smem3);

    prep_kernel<<<NCHK, 128, smem1>>>(q, k, v, beta);
    scan_kernel<<<dim3(NDVB, BHh), 1024, smem2>>>(out);
    epi_kernel<<<dim3(NCH, BHh), 256, smem3>>>(out);
}

// round 15
// speedup vs baseline: 1.0774x; 1.0635x over previous
#include <cuda_runtime.h>

#define Ll 4096
#define Dd 128
#define Cc 32
#define NCH 128
#define BHh 16
#define DVB 16
#define NDVB 8
#define ELEMS (BHh*Ll*Dd)
#define O_ELEMS ((size_t)ELEMS)
#define NCHK (BHh*NCH)

typedef unsigned long long u64t;
__device__ __forceinline__ u64t pk2s(float a){
    u64t r; asm("mov.b64 %0,{%1,%1};" : "=l"(r) : "f"(a)); return r;
}
__device__ __forceinline__ u64t f2(u64t a, u64t b, u64t c){
    u64t d; asm("fma.rn.f32x2 %0,%1,%2,%3;" : "=l"(d) : "l"(a), "l"(b), "l"(c)); return d;
}
__device__ __forceinline__ float2 up2(u64t p){
    float lo, hi; asm("mov.b64 {%0,%1},%2;" : "=f"(lo), "=f"(hi) : "l"(p));
    return make_float2(lo, hi);
}

// Scratch (__device__ globals)
__device__ float g_qn  [ELEMS];               // q normalized (epilogue)
__device__ float g_u   [ELEMS];               // u = T(v*beta) row-major (scan)
__device__ float g_wT36[NCHK*4608];           // per chunk: w^T [128][36] padded
__device__ float g_kT36[NCHK*4608];           // per chunk: k^T [128][36] padded
__device__ float g_att [NCHK*1024];           // attn_local (epilogue)
__device__ float g_S   [(size_t)NCHK*16384];  // per chunk: S_i col-major [c][d]
__device__ float g_u2  [NCHK*4096];           // per chunk: u' ROW-major [r][c]

__device__ __forceinline__ unsigned smem_u32(const void* p){
    unsigned a;
    asm("{ .reg .u64 t; cvta.to.shared.u64 t, %1; cvt.u32.u64 %0, t; }"
        : "=r"(a) : "l"(p));
    return a;
}
__device__ __forceinline__ void mbar_init(unsigned mbar, unsigned cnt){
    asm volatile("mbarrier.init.shared.b64 [%0], %1;" :: "r"(mbar), "r"(cnt) : "memory");
}
__device__ __forceinline__ void mbar_expect_tx(unsigned mbar, unsigned bytes){
    asm volatile("mbarrier.arrive.expect_tx.shared.b64 _, [%0], %1;"
                 :: "r"(mbar), "r"(bytes) : "memory");
}
__device__ __forceinline__ void tma_bulk_g2s(unsigned dst, const void* src,
                                             unsigned bytes, unsigned mbar){
    asm volatile("cp.async.bulk.shared::cta.global.mbarrier::complete_tx::bytes "
                 "[%0], [%1], %2, [%3];"
                 :: "r"(dst), "l"(src), "r"(bytes), "r"(mbar) : "memory");
}
__device__ __forceinline__ void mbar_wait(unsigned mbar, unsigned parity){
    asm volatile("{\n\t.reg .pred P;\n"
                 "WAIT_%=:\n\t"
                 "mbarrier.try_wait.parity.acquire.cta.shared::cta.b64 P, [%0], %1;\n\t"
                 "@!P bra WAIT_%=;\n\t}"
                 :: "r"(mbar), "r"(parity) : "memory");
}

// ----------------------------------------------------------------------------
// Kernel 1: per-chunk preprocessing. grid = 2048, block = 128  (616us winner)
// ----------------------------------------------------------------------------
__global__ __launch_bounds__(128) void prep_kernel(
    const float* __restrict__ q, const float* __restrict__ k,
    const float* __restrict__ v, const float* __restrict__ beta)
{
    extern __shared__ float sm1[];
    float* sqT   = sm1;                // [128][33]
    float* skT   = sqT + 4224;         // [128][33]
    float* svb   = skT + 4224;         // [32][128]
    float* sA    = svb + 4096;         // [32][33]
    float* sbeta = sA  + 1056;         // [32]

    const int tid  = threadIdx.x;
    const int lane = tid & 31;
    const int warp = tid >> 5;
    const int bh = blockIdx.x >> 7;
    const int ci = blockIdx.x & 127;
    const int chk = blockIdx.x;
    const size_t base = ((size_t)bh*Ll + (size_t)ci*Cc)*Dd;

    for (int r = warp*8; r < warp*8 + 8; ++r) {
        float bet = beta[(size_t)bh*Ll + ci*Cc + r];
        const float4 xq = *(const float4*)(q + base + r*Dd + lane*4);
        const float4 xk = *(const float4*)(k + base + r*Dd + lane*4);
        const float4 xv = *(const float4*)(v + base + r*Dd + lane*4);
        float s2q = xq.x*xq.x + xq.y*xq.y + xq.z*xq.z + xq.w*xq.w;
        float s2k = xk.x*xk.x + xk.y*xk.y + xk.z*xk.z + xk.w*xk.w;
        #pragma unroll
        for (int o = 16; o; o >>= 1) {
            s2q += __shfl_xor_sync(0xffffffffu, s2q, o);
            s2k += __shfl_xor_sync(0xffffffffu, s2k, o);
        }
        float iq = rsqrtf(s2q + 1e-6f);
        float ik = rsqrtf(s2k + 1e-6f);
        float4 nq = make_float4(xq.x*iq, xq.y*iq, xq.z*iq, xq.w*iq);
        float4 nk = make_float4(xk.x*ik, xk.y*ik, xk.z*ik, xk.w*ik);
        *(float4*)(g_qn + base + r*Dd + lane*4) = nq;
        const int d0 = lane*4;
        sqT[(d0+0)*33 + r] = nq.x; sqT[(d0+1)*33 + r] = nq.y;
        sqT[(d0+2)*33 + r] = nq.z; sqT[(d0+3)*33 + r] = nq.w;
        skT[(d0+0)*33 + r] = nk.x; skT[(d0+1)*33 + r] = nk.y;
        skT[(d0+2)*33 + r] = nk.z; skT[(d0+3)*33 + r] = nk.w;
        *(float4*)(svb + r*Dd + d0) = make_float4(xv.x*bet, xv.y*bet, xv.z*bet, xv.w*bet);
        if (lane == 0) sbeta[r] = bet;
    }
    __syncthreads();

    // k^T padded [128][36] (TMA target layout)
    {
        const int d = tid;
        #pragma unroll
        for (int r4 = 0; r4 < 32; r4 += 4) {
            *(float4*)&g_kT36[(size_t)chk*4608 + d*36 + r4] = make_float4(
                skT[d*33+r4], skT[d*33+r4+1], skT[d*33+r4+2], skT[d*33+r4+3]);
        }
    }

    // A = -beta_i (k_i.k_j) strict-lower ; E = q_i.k_j incl-lower -> g_att
    {
        const int i0 = (tid >> 3) * 2;
        const int j0 = (tid & 7) * 4;
        float a00=0,a01=0,a02=0,a03=0,a10=0,a11=0,a12=0,a13=0;
        float e00=0,e01=0,e02=0,e03=0,e10=0,e11=0,e12=0,e13=0;
        #pragma unroll 4
        for (int d = 0; d < Dd; ++d) {
            const float* kc = skT + d*33;
            const float* qc = sqT + d*33;
            float b0=kc[j0], b1=kc[j0+1], b2=kc[j0+2], b3=kc[j0+3];
            float ka0=kc[i0], ka1=kc[i0+1], qa0=qc[i0], qa1=qc[i0+1];
            a00+=ka0*b0; a01+=ka0*b1; a02+=ka0*b2; a03+=ka0*b3;
            a10+=ka1*b0; a11+=ka1*b1; a12+=ka1*b2; a13+=ka1*b3;
            e00+=qa0*b0; e01+=qa0*b1; e02+=qa0*b2; e03+=qa0*b3;
            e10+=qa1*b0; e11+=qa1*b1; e12+=qa1*b2; e13+=qa1*b3;
        }
        float nb0 = -sbeta[i0], nb1 = -sbeta[i0+1];
        sA[(i0  )*33+j0  ] = (j0  <i0  ) ? nb0*a00 : 0.f;
        sA[(i0  )*33+j0+1] = (j0+1<i0  ) ? nb0*a01 : 0.f;
        sA[(i0  )*33+j0+2] = (j0+2<i0  ) ? nb0*a02 : 0.f;
        sA[(i0  )*33+j0+3] = (j0+3<i0  ) ? nb0*a03 : 0.f;
        sA[(i0+1)*33+j0  ] = (j0  <i0+1) ? nb1*a10 : 0.f;
        sA[(i0+1)*33+j0+1] = (j0+1<i0+1) ? nb1*a11 : 0.f;
        sA[(i0+1)*33+j0+2] = (j0+2<i0+1) ? nb1*a12 : 0.f;
        sA[(i0+1)*33+j0+3] = (j0+3<i0+1) ? nb1*a13 : 0.f;
        float* ga = g_att + (size_t)chk*1024;
        ga[(i0  )*Cc+j0  ] = (j0  <=i0  ) ? e00 : 0.f;
        ga[(i0  )*Cc+j0+1] = (j0+1<=i0  ) ? e01 : 0.f;
        ga[(i0  )*Cc+j0+2] = (j0+2<=i0  ) ? e02 : 0.f;
        ga[(i0  )*Cc+j0+3] = (j0+3<=i0  ) ? e03 : 0.f;
        ga[(i0+1)*Cc+j0  ] = (j0  <=i0+1) ? e10 : 0.f;
        ga[(i0+1)*Cc+j0+1] = (j0+1<=i0+1) ? e11 : 0.f;
        ga[(i0+1)*Cc+j0+2] = (j0+2<=i0+1) ? e12 : 0.f;
        ga[(i0+1)*Cc+j0+3] = (j0+3<=i0+1) ? e13 : 0.f;
    }
    __syncthreads();

    // forward substitution (warp 0), then += I
    if (warp == 0) {
        for (int i = 1; i < 32; ++i) {
            float rv  = sA[i*33 + lane];
            float acc = rv;
            for (int j = 0; j < i; ++j)
                acc += __shfl_sync(0xffffffffu, rv, j) * sA[j*33 + lane];
            sA[i*33 + lane] = acc;
            __syncwarp();
        }
        sA[lane*33 + lane] += 1.0f;
    }
    __syncthreads();

    // u = T(v*beta) row-major ; w^T padded [128][36]
    {
        const int d = tid;
        #pragma unroll
        for (int rb = 0; rb < 4; ++rb) {
            const int r0 = rb*8;
            float ar[8];
            #pragma unroll
            for (int rr = 0; rr < 8; ++rr) ar[rr] = sA[(r0+rr)*33 + lane];
            float au[8] = {0,0,0,0,0,0,0,0};
            float aw[8] = {0,0,0,0,0,0,0,0};
            for (int j = 0; j < 32; ++j) {
                float vb = svb[j*Dd + d];
                float kb = skT[d*33 + j] * sbeta[j];
                #pragma unroll
                for (int rr = 0; rr < 8; ++rr) {
                    float a = __shfl_sync(0xffffffffu, ar[rr], j);
                    au[rr] += a*vb;
                    aw[rr] += a*kb;
                }
            }
            #pragma unroll
            for (int rr = 0; rr < 8; ++rr)
                g_u[base + (size_t)(r0+rr)*Dd + d] = au[rr];
            *(float4*)&g_wT36[(size_t)chk*4608 + d*36 + r0    ] = make_float4(aw[0],aw[1],aw[2],aw[3]);
            *(float4*)&g_wT36[(size_t)chk*4608 + d*36 + r0 + 4] = make_float4(aw[4],aw[5],aw[6],aw[7]);
        }
    }
}

// ----------------------------------------------------------------------------
// Kernel 2: sequential scan. grid = (8,16), block = 512. TMA staging +
// packed f32x2 compute (no repacking: all paired operands 8B-aligned in smem).
// ----------------------------------------------------------------------------
#define WST 36
#define SST 20
#define TILE_F 4608                 // floats per (w or k) buffer
#define TILE_B 18432                // bytes per tile

__global__ __launch_bounds__(512, 1) void scan_kernel(float* __restrict__ out)
{
    extern __shared__ float sm2[];
    float* swT = sm2;                   // [2][128][36] w^T
    float* skT = swT + 2*TILE_F;        // [2][128][36] k^T
    float* sS  = skT + 2*TILE_F;        // [128][20]
    float* sYp = sS  + 2560;            // [8][32][20]
    float* su2 = sYp + 5120;            // [32][20]
    float* smb = su2 + 640;             // mbarriers (2 x 8B)

    const int cb = blockIdx.x;
    const int bh = blockIdx.y;
    const int colbase = cb * DVB;
    const int tid  = threadIdx.x;
    const int lane = tid & 31;
    const int warp = tid >> 5;

    const unsigned sw_u32 = smem_u32(swT);
    const unsigned sk_u32 = smem_u32(skT);
    const unsigned mb_u32 = smem_u32(smb);

    // Y roles: dq = 16-d slice (0..7), cg8 = col half {0,8}; lane = r
    const int dq  = warp >> 1;
    const int cg8 = (warp & 1) * 8;
    // update roles: lane owns S[sd][uc4..+3]
    const int sd  = (warp >> 2)*32 + lane;
    const int uc4 = (warp & 3) * 4;
    // u' roles: thread -> (r = tid>>4, c = tid&15)
    const int upr = tid >> 4;
    const int upc = tid & 15;

    u64t s01 = 0ull, s23 = 0ull;        // packed S tile: cols uc4..+3
    for (int i = tid; i < 2560; i += 512) sS[i] = 0.f;

    // init mbarriers + first fill
    if (tid == 0) { mbar_init(mb_u32, 1); mbar_init(mb_u32 + 8, 1); }
    __syncthreads();
    if (tid == 0) {
        const size_t tb = (size_t)(bh*NCH)*TILE_F;
        mbar_expect_tx(mb_u32, 2*TILE_B);
        tma_bulk_g2s(sw_u32, g_wT36 + tb, TILE_B, mb_u32);
        tma_bulk_g2s(sk_u32, g_kT36 + tb, TILE_B, mb_u32);
    }
    float ruu = g_u[((size_t)bh*Ll + upr)*Dd + colbase + upc];

    for (int ci = 0; ci < NCH; ++ci) {
        const int buf = ci & 1;
        const int chk = bh*NCH + ci;

        // issue fill for chunk ci+1 into the other buffer
        if (tid == 0 && ci + 1 < NCH) {
            const int b2 = (ci + 1) & 1;
            const size_t tb = (size_t)(chk + 1)*TILE_F;
            mbar_expect_tx(mb_u32 + b2*8, 2*TILE_B);
            tma_bulk_g2s(sw_u32 + b2*TILE_B, g_wT36 + tb, TILE_B, mb_u32 + b2*8);
            tma_bulk_g2s(sk_u32 + b2*TILE_B, g_kT36 + tb, TILE_B, mb_u32 + b2*8);
        }
        // prefetch next u element
        float ru_next = ruu;
        if (ci + 1 < NCH)
            ru_next = g_u[((size_t)bh*Ll + (size_t)(ci+1)*Cc + upr)*Dd + colbase + upc];

        // wait for this chunk's tiles
        mbar_wait(mb_u32 + buf*8, (unsigned)((ci >> 1) & 1));

        // persist S_i (pre-chunk), col-major [c][d]
        {
            float2 a = up2(s01), b = up2(s23);
            float* gs = g_S + (size_t)chk*16384 + (size_t)(colbase + uc4)*128 + sd;
            gs[0] = a.x; gs[128] = a.y; gs[256] = b.x; gs[384] = b.y;
        }

        // Y: partial of w(32x128)@S(128x16); warp: d in [dq*16,+16), 8 cols
        {
            const float* xw = swT + buf*TILE_F;
            u64t y0=0ull, y1=0ull, y2=0ull, y3=0ull;
            #pragma unroll
            for (int j = 0; j < 16; ++j) {
                const int jd = dq*16 + j;
                u64t xx = pk2s(xw[jd*WST + lane]);
                ulonglong2 sa = *(const ulonglong2*)&sS[jd*SST + cg8];
                ulonglong2 sb = *(const ulonglong2*)&sS[jd*SST + cg8 + 4];
                y0 = f2(xx, sa.x, y0); y1 = f2(xx, sa.y, y1);
                y2 = f2(xx, sb.x, y2); y3 = f2(xx, sb.y, y3);
            }
            ulonglong2 o1; o1.x = y0; o1.y = y1;
            ulonglong2 o2; o2.x = y2; o2.y = y3;
            *(ulonglong2*)&sYp[dq*640 + lane*SST + cg8    ] = o1;
            *(ulonglong2*)&sYp[dq*640 + lane*SST + cg8 + 4] = o2;
        }
        __syncthreads();

        // u' = u - w@S  (all 512 threads, one element each)
        {
            float acc = ruu;
            #pragma unroll
            for (int d8 = 0; d8 < 8; ++d8)
                acc -= sYp[d8*640 + upr*SST + upc];
            su2[upr*SST + upc] = acc;
            g_u2[(size_t)chk*4096 + upr*128 + colbase + upc] = acc;   // row-major
        }
        __syncthreads();

        // S += k^T @ u'  (packed f32x2 accumulators; conflict-free vec loads)
        {
            const float* kp = skT + buf*TILE_F + sd*WST;
            #pragma unroll
            for (int r4 = 0; r4 < 8; ++r4) {
                float4 k4 = *(const float4*)(kp + r4*4);
                ulonglong2 u0 = *(const ulonglong2*)&su2[(r4*4    )*SST + uc4];
                ulonglong2 u1 = *(const ulonglong2*)&su2[(r4*4 + 1)*SST + uc4];
                ulonglong2 u2 = *(const ulonglong2*)&su2[(r4*4 + 2)*SST + uc4];
                ulonglong2 u3 = *(const ulonglong2*)&su2[(r4*4 + 3)*SST + uc4];
                u64t kk;
                kk = pk2s(k4.x); s01 = f2(kk, u0.x, s01); s23 = f2(kk, u0.y, s23);
                kk = pk2s(k4.y); s01 = f2(kk, u1.x, s01); s23 = f2(kk, u1.y, s23);
                kk = pk2s(k4.z); s01 = f2(kk, u2.x, s01); s23 = f2(kk, u2.y, s23);
                kk = pk2s(k4.w); s01 = f2(kk, u3.x, s01); s23 = f2(kk, u3.y, s23);
            }
            ulonglong2 sv; sv.x = s01; sv.y = s23;
            *(ulonglong2*)&sS[sd*SST + uc4] = sv;
        }
        ruu = ru_next;
        __syncthreads();
    }

    // final S -> out
    {
        float2 a = up2(s01), b = up2(s23);
        *(float4*)&out[O_ELEMS + ((size_t)bh*Dd + sd)*Dd + colbase + uc4] =
            make_float4(a.x, a.y, b.x, b.y);
    }
}

// ----------------------------------------------------------------------------
// Kernel 3: epilogue o = q@S_i + A@u'_i. grid = (NCH, BHh), block = 256.
// ----------------------------------------------------------------------------
#define AST 36

__global__ __launch_bounds__(256) void epi_kernel(float* __restrict__ out)
{
    extern __shared__ float sm3[];
    float* sS = sm3;              // [128][132]
    float* sq = sS + 128*132;     // [32][132]
    float* su = sq + 32*132;      // [32][132]
    float* sA = su + 32*132;      // [32][36]

    const int ci = blockIdx.x;
    const int bh = blockIdx.y;
    const int chk = bh*NCH + ci;
    const int tid = threadIdx.x;
    const size_t qbase = ((size_t)bh*Ll + (size_t)ci*Cc)*Dd;

    // stage S (col-major gmem -> row-major smem)
    {
        const int c = tid >> 1;
        const int db = (tid & 1) * 64;
        const float* gs = g_S + (size_t)chk*16384 + (size_t)c*128 + db;
        #pragma unroll
        for (int i = 0; i < 16; ++i) {
            float4 f = *(const float4*)(gs + i*4);
            int d = db + i*4;
            sS[(d  )*132 + c] = f.x; sS[(d+1)*132 + c] = f.y;
            sS[(d+2)*132 + c] = f.z; sS[(d+3)*132 + c] = f.w;
        }
    }
    // stage q (row-major)
    {
        #pragma unroll
        for (int t = 0; t < 4; ++t) {
            int i4 = (tid + t*256) * 4;
            float4 f = *(const float4*)(g_qn + qbase + i4);
            *(float4*)&sq[(i4 >> 7)*132 + (i4 & 127)] = f;
        }
    }
    // stage u' (row-major, straight copy)
    {
        #pragma unroll
        for (int t = 0; t < 4; ++t) {
            int i4 = (tid + t*256) * 4;
            float4 f = *(const float4*)(g_u2 + (size_t)chk*4096 + i4);
            *(float4*)&su[(i4 >> 7)*132 + (i4 & 127)] = f;
        }
    }
    // stage A (stride 36)
    {
        int i4 = tid * 4;
        float4 f = *(const float4*)(g_att + (size_t)chk*1024 + i4);
        *(float4*)&sA[(i4 >> 5)*AST + (i4 & 31)] = f;
    }
    __syncthreads();

    const int m0 = (tid >> 4) * 2;
    const int m1 = m0 + 1;
    const int cbk = (tid & 15) * 8;
    float4 a00 = make_float4(0,0,0,0), a01 = a00, a10 = a00, a11 = a00;
    #pragma unroll 8
    for (int d = 0; d < 128; ++d) {
        float q0 = sq[m0*132 + d];
        float q1 = sq[m1*132 + d];
        float4 s0 = *(const float4*)&sS[d*132 + cbk];
        float4 s1 = *(const float4*)&sS[d*132 + cbk + 4];
        a00.x += q0*s0.x; a00.y += q0*s0.y; a00.z += q0*s0.z; a00.w += q0*s0.w;
        a01.x += q0*s1.x; a01.y += q0*s1.y; a01.z += q0*s1.z; a01.w += q0*s1.w;
        a10.x += q1*s0.x; a10.y += q1*s0.y; a10.z += q1*s0.z; a10.w += q1*s0.w;
        a11.x += q1*s1.x; a11.y += q1*s1.y; a11.z += q1*s1.z; a11.w += q1*s1.w;
    }
    #pragma unroll 8
    for (int j = 0; j < 32; ++j) {
        float p0 = sA[m0*AST + j];
        float p1 = sA[m1*AST + j];
        float4 u0 = *(const float4*)&su[j*132 + cbk];
        float4 u1 = *(const float4*)&su[j*132 + cbk + 4];
        a00.x += p0*u0.x; a00.y += p0*u0.y; a00.z += p0*u0.z; a00.w += p0*u0.w;
        a01.x += p0*u1.x; a01.y += p0*u1.y; a01.z += p0*u1.z; a01.w += p0*u1.w;
        a10.x += p1*u0.x; a10.y += p1*u0.y; a10.z += p1*u0.z; a10.w += p1*u0.w;
        a11.x += p1*u1.x; a11.y += p1*u1.y; a11.z += p1*u1.z; a11.w += p1*u1.w;
    }
    float* o0 = out + qbase + (size_t)m0*Dd + cbk;
    float* o1 = out + qbase + (size_t)m1*Dd + cbk;
    *(float4*)(o0)     = a00; *(float4*)(o0 + 4) = a01;
    *(float4*)(o1)     = a10; *(float4*)(o1 + 4) = a11;
}

// ----------------------------------------------------------------------------
extern "C" void kernel_launch(void* const* d_in, const int* in_sizes, int n_in,
                              void* d_out, int out_size)
{
    const float* q    = (const float*)d_in[0];
    const float* k    = (const float*)d_in[1];
    const float* v    = (const float*)d_in[2];
    const float* beta = (const float*)d_in[3];
    float* out = (float*)d_out;

    const int smem1 = (2*4224 + 4096 + 1056 + 32) * 4;                 // 54528
    const int smem2 = (4*TILE_F + 2560 + 5120 + 640 + 8) * 4;          // 107040
    const int smem3 = (128*132 + 32*132 + 32*132 + 32*AST) * 4;        // 105984
    cudaFuncSetAttribute(prep_kernel, cudaFuncAttributeMaxDynamicSharedMemorySize, smem1);
    cudaFuncSetAttribute(scan_kernel, cudaFuncAttributeMaxDynamicSharedMemorySize, smem2);
    cudaFuncSetAttribute(epi_kernel,  cudaFuncAttributeMaxDynamicSharedMemorySize, smem3);

    prep_kernel<<<NCHK, 128, smem1>>>(q, k, v, beta);
    scan_kernel<<<dim3(NDVB, BHh), 512, smem2>>>(out);
    epi_kernel<<<dim3(NCH, BHh), 256, smem3>>>(out);
}